// round 2
// baseline (speedup 1.0000x reference)
#include <cuda_runtime.h>
#include <math_constants.h>

#define BB 8
#define N1C 2048
#define N2C 2048
#define DD 120
#define NROW (BB * N1C)

#define TM 64
#define TN 64

// ---------------- scratch (device globals; no allocation) ----------------
__device__ float g_Qt[(size_t)BB * DD * N1C];  // [b][d][n1]  (d-major!)
__device__ float g_Kt[(size_t)BB * DD * N2C];  // [b][d][n2]
__device__ float g_V [(size_t)BB * N2C * DD];  // [b][n2][d]  (natural)
__device__ float g_M [BB * N1C];               // row max
__device__ float g_L [BB * N1C];               // row sum-exp

// ---------------- kernel 1: QKV projection ----------------
// grid (NROW/32, 3), block 128. smem: Wt[120][124] + xs[32][120]
#define PROJ_SMEM ((120 * 124 + 32 * 120) * 4)

__global__ void proj_kernel(const float* __restrict__ x1,
                            const float* __restrict__ x2,
                            const float* __restrict__ Wq,
                            const float* __restrict__ Wk,
                            const float* __restrict__ Wv)
{
    extern __shared__ float sm[];
    float* Wt = sm;              // [e][d] stride 124 (conflict-free float4 reads)
    float* xs = sm + 120 * 124;  // [32][120]

    const int which = blockIdx.y;
    const float* X = (which == 0) ? x1 : x2;
    const float* W = (which == 0) ? Wq : (which == 1 ? Wk : Wv);

    const int row0 = blockIdx.x * 32;
    const int tid = threadIdx.x;

    for (int idx = tid; idx < DD * DD; idx += 128) {
        int d = idx / DD, e = idx % DD;
        Wt[e * 124 + d] = W[idx];
    }
    for (int idx = tid; idx < 32 * DD; idx += 128) {
        xs[idx] = X[(size_t)row0 * DD + idx];
    }
    __syncthreads();

    if (tid < DD) {
        const int e = tid;
        float acc[32];
        #pragma unroll
        for (int r = 0; r < 32; r++) acc[r] = 0.f;

        for (int d = 0; d < DD; d += 4) {
            float4 w4 = *(const float4*)&Wt[e * 124 + d];
            #pragma unroll
            for (int r = 0; r < 32; r++) {
                float4 x4 = *(const float4*)&xs[r * DD + d];
                acc[r] = fmaf(x4.x, w4.x, acc[r]);
                acc[r] = fmaf(x4.y, w4.y, acc[r]);
                acc[r] = fmaf(x4.z, w4.z, acc[r]);
                acc[r] = fmaf(x4.w, w4.w, acc[r]);
            }
        }

        if (which == 2) {
            #pragma unroll 4
            for (int r = 0; r < 32; r++)
                g_V[(size_t)(row0 + r) * DD + e] = acc[r];
        } else {
            float* dst = (which == 0) ? g_Qt : g_Kt;
            #pragma unroll 4
            for (int r = 0; r < 32; r++) {
                int rr = row0 + r;
                int b = rr >> 11;       // / 2048
                int n = rr & 2047;
                dst[((size_t)b * DD + e) * N2C + n] = acc[r];
            }
        }
    }
}

// ---------------- kernel 2: scores + online softmax stats ----------------
// grid (N1/64, B), block 256 (tx 0..15, ty 0..15). smem: Qt[120][64] + Kt[120][64]
#define SC_SMEM ((DD * TM + DD * TN) * 4)

__global__ void score_kernel(const int* __restrict__ mask,
                             float* __restrict__ attn /* raw scores staged here */)
{
    extern __shared__ float sm[];
    float* Qt = sm;            // [d][r] : conflict-free float4 read at 4*ty
    float* Kt = sm + DD * TM;  // [d][c] : conflict-free float4 read at 4*tx

    const int b  = blockIdx.y;
    const int i0 = blockIdx.x * TM;
    const int tid = threadIdx.x;
    const int tx = tid & 15, ty = tid >> 4;

    for (int idx = tid; idx < DD * TM; idx += 256) {
        int d = idx / TM, r = idx % TM;
        Qt[idx] = g_Qt[((size_t)b * DD + d) * N1C + i0 + r];
    }

    const float scale = 0.09128709291752768f;  // 1/sqrt(120)
    float m_run[4], l_run[4];
    #pragma unroll
    for (int r = 0; r < 4; r++) { m_run[r] = -CUDART_INF_F; l_run[r] = 0.f; }

    for (int j0 = 0; j0 < N2C; j0 += TN) {
        __syncthreads();
        for (int idx = tid; idx < DD * TN; idx += 256) {
            int d = idx / TN, c = idx % TN;
            Kt[idx] = g_Kt[((size_t)b * DD + d) * N2C + j0 + c];
        }
        __syncthreads();

        float acc[4][4];
        #pragma unroll
        for (int r = 0; r < 4; r++)
            #pragma unroll
            for (int c = 0; c < 4; c++) acc[r][c] = 0.f;

        #pragma unroll 4
        for (int d = 0; d < DD; d++) {
            float4 q4 = *(const float4*)&Qt[d * TM + 4 * ty];
            float4 k4 = *(const float4*)&Kt[d * TN + 4 * tx];
            float q[4] = {q4.x, q4.y, q4.z, q4.w};
            float k[4] = {k4.x, k4.y, k4.z, k4.w};
            #pragma unroll
            for (int r = 0; r < 4; r++)
                #pragma unroll
                for (int c = 0; c < 4; c++)
                    acc[r][c] = fmaf(q[r], k[c], acc[r][c]);
        }

        // scale + mask, then online stats, then stream raw scores to gmem
        #pragma unroll
        for (int r = 0; r < 4; r++) {
            int gi = i0 + 4 * ty + r;
            size_t gidx = ((size_t)(b * N1C + gi)) * N2C + j0 + 4 * tx;
            int4 mv = *(const int4*)&mask[gidx];
            float s0 = mv.x ? acc[r][0] * scale : -CUDART_INF_F;
            float s1 = mv.y ? acc[r][1] * scale : -CUDART_INF_F;
            float s2 = mv.z ? acc[r][2] * scale : -CUDART_INF_F;
            float s3 = mv.w ? acc[r][3] * scale : -CUDART_INF_F;

            float tmax = fmaxf(fmaxf(s0, s1), fmaxf(s2, s3));
            #pragma unroll
            for (int o = 8; o; o >>= 1)
                tmax = fmaxf(tmax, __shfl_xor_sync(0xffffffffu, tmax, o));
            float m_new = fmaxf(m_run[r], tmax);

            float se = __expf(s0 - m_new) + __expf(s1 - m_new)
                     + __expf(s2 - m_new) + __expf(s3 - m_new);
            #pragma unroll
            for (int o = 8; o; o >>= 1)
                se += __shfl_xor_sync(0xffffffffu, se, o);

            l_run[r] = l_run[r] * __expf(m_run[r] - m_new) + se;
            m_run[r] = m_new;

            *(float4*)&attn[gidx] = make_float4(s0, s1, s2, s3);
        }
    }

    if (tx == 0) {
        #pragma unroll
        for (int r = 0; r < 4; r++) {
            int gi = b * N1C + i0 + 4 * ty + r;
            g_M[gi] = m_run[r];
            g_L[gi] = l_run[r];
        }
    }
}

// ---------------- kernel 3: normalize attn in place + O = P·V ----------------
// grid (N1/64, B), block 256. smem: Ps[64][64] + Vs[64][128] + m[64] + linv[64]
#define PV_SMEM ((TM * TN + TN * 128 + 2 * TM) * 4)

__global__ void pv_kernel(float* __restrict__ attn, float* __restrict__ out)
{
    extern __shared__ float sm[];
    float* Ps   = sm;                 // [r][j]
    float* Vs   = Ps + TM * TN;       // [j][128], cols 120..127 zero
    float* mrow = Vs + TN * 128;      // [64]
    float* lirow = mrow + TM;         // [64] holds 1/l

    const int b  = blockIdx.y;
    const int i0 = blockIdx.x * TM;
    const int tid = threadIdx.x;
    const int tx = tid & 15, ty = tid >> 4;

    for (int idx = tid; idx < TM; idx += 256) {
        mrow[idx]  = g_M[b * N1C + i0 + idx];
        lirow[idx] = 1.0f / g_L[b * N1C + i0 + idx];
    }

    float acc[4][8];
    #pragma unroll
    for (int r = 0; r < 4; r++)
        #pragma unroll
        for (int c = 0; c < 8; c++) acc[r][c] = 0.f;

    for (int j0 = 0; j0 < N2C; j0 += TN) {
        __syncthreads();
        // V tile
        for (int idx = tid; idx < TN * 128; idx += 256) {
            int j = idx >> 7, e = idx & 127;
            Vs[idx] = (e < DD) ? g_V[((size_t)(b * N2C + j0 + j)) * DD + e] : 0.f;
        }
        // raw scores -> p = exp(s-m)/l; write final attn + stash in smem
        #pragma unroll
        for (int f = 0; f < 4; f++) {
            int f4 = f * 256 + tid;        // 1024 float4s in the 64x64 tile
            int r  = f4 >> 4;
            int c4 = (f4 & 15) * 4;
            size_t gidx = ((size_t)(b * N1C + i0 + r)) * N2C + j0 + c4;
            float4 sv = *(const float4*)&attn[gidx];
            float m = mrow[r], li = lirow[r];
            float4 p;
            p.x = __expf(sv.x - m) * li;
            p.y = __expf(sv.y - m) * li;
            p.z = __expf(sv.z - m) * li;
            p.w = __expf(sv.w - m) * li;
            *(float4*)&attn[gidx] = p;
            *(float4*)&Ps[r * TN + c4] = p;
        }
        __syncthreads();

        #pragma unroll 4
        for (int j = 0; j < TN; j++) {
            float4 v0 = *(const float4*)&Vs[j * 128 + 8 * tx];
            float4 v1 = *(const float4*)&Vs[j * 128 + 8 * tx + 4];
            #pragma unroll
            for (int rr = 0; rr < 4; rr++) {
                float p = Ps[(4 * ty + rr) * TN + j];
                acc[rr][0] = fmaf(p, v0.x, acc[rr][0]);
                acc[rr][1] = fmaf(p, v0.y, acc[rr][1]);
                acc[rr][2] = fmaf(p, v0.z, acc[rr][2]);
                acc[rr][3] = fmaf(p, v0.w, acc[rr][3]);
                acc[rr][4] = fmaf(p, v1.x, acc[rr][4]);
                acc[rr][5] = fmaf(p, v1.y, acc[rr][5]);
                acc[rr][6] = fmaf(p, v1.z, acc[rr][6]);
                acc[rr][7] = fmaf(p, v1.w, acc[rr][7]);
            }
        }
    }

    const int e0 = 8 * tx;
    #pragma unroll
    for (int rr = 0; rr < 4; rr++) {
        int gi = i0 + 4 * ty + rr;
        #pragma unroll
        for (int c = 0; c < 8; c++) {
            int e = e0 + c;
            if (e < DD)
                out[((size_t)(b * N1C + gi)) * DD + e] = acc[rr][c];
        }
    }
}

// ---------------- launch ----------------
extern "C" void kernel_launch(void* const* d_in, const int* in_sizes, int n_in,
                              void* d_out, int out_size)
{
    const float* x1  = (const float*)d_in[0];
    const float* x2  = (const float*)d_in[1];
    const int*   msk = (const int*)  d_in[2];
    const float* Wq  = (const float*)d_in[3];
    const float* Wk  = (const float*)d_in[4];
    const float* Wv  = (const float*)d_in[5];

    float* outO = (float*)d_out;                       // [B,N1,D]
    float* outP = outO + (size_t)BB * N1C * DD;        // [B,N1,N2]

    cudaFuncSetAttribute(proj_kernel,  cudaFuncAttributeMaxDynamicSharedMemorySize, PROJ_SMEM);
    cudaFuncSetAttribute(score_kernel, cudaFuncAttributeMaxDynamicSharedMemorySize, SC_SMEM);
    cudaFuncSetAttribute(pv_kernel,    cudaFuncAttributeMaxDynamicSharedMemorySize, PV_SMEM);

    proj_kernel <<<dim3(NROW / 32, 3),      128, PROJ_SMEM>>>(x1, x2, Wq, Wk, Wv);
    score_kernel<<<dim3(N1C / TM, BB),      256, SC_SMEM  >>>(msk, outP);
    pv_kernel   <<<dim3(N1C / TM, BB),      256, PV_SMEM  >>>(outP, outO);
}

// round 3
// speedup vs baseline: 1.5505x; 1.5505x over previous
#include <cuda_runtime.h>
#include <math_constants.h>

#define BB 8
#define N1C 2048
#define N2C 2048
#define DD 120
#define NROW (BB * N1C)

#define TI 64          // i-rows per block (score/pv)
#define TJ 64          // j-cols per pv inner tile

// ---------------- scratch (device globals; no allocation) ----------------
__device__ float g_Qt[(size_t)BB * DD * N1C];  // [b][d][n1]  (d-major)
__device__ float g_Kt[(size_t)BB * DD * N2C];  // [b][d][n2]  (d-major)
__device__ float g_V [(size_t)BB * N2C * DD];  // [b][n2][d]  (natural)
__device__ float g_M [BB * N1C];               // row max
__device__ float g_L [BB * N1C];               // row sum-exp

// ================= kernel 1: QKV projection =================
// grid (NROW/64, 3), block 256 (tx 16, ty 16). tile: 64 rows x 120 cols.
// microtile 4 rows x 8 cols (col groups {4tx, 64+4tx}), d chunks of 40.
// smem: union( Xs[64][40] + Ws[40][132],  Os[64][131] )
#define PROJ_XS  (64 * 40)
#define PROJ_WS  (40 * 132)
#define PROJ_OS  (64 * 131)
#define PROJ_SMEM_FLOATS ((PROJ_XS + PROJ_WS) > PROJ_OS ? (PROJ_XS + PROJ_WS) : PROJ_OS)
#define PROJ_SMEM (PROJ_SMEM_FLOATS * 4)

__global__ __launch_bounds__(256) void proj_kernel(
    const float* __restrict__ x1, const float* __restrict__ x2,
    const float* __restrict__ Wq, const float* __restrict__ Wk,
    const float* __restrict__ Wv)
{
    extern __shared__ float sm[];
    float* Xs = sm;               // [r][40]
    float* Ws = sm + PROJ_XS;     // [d][132], cols >=120 zero
    float* Os = sm;               // reuse, [r][131]

    const int which = blockIdx.y;
    const float* X = (which == 0) ? x1 : x2;
    const float* W = (which == 0) ? Wq : (which == 1 ? Wk : Wv);

    const int row0 = blockIdx.x * 64;
    const int tid = threadIdx.x;
    const int tx = tid & 15, ty = tid >> 4;

    float acc[4][8];
    #pragma unroll
    for (int r = 0; r < 4; r++)
        #pragma unroll
        for (int c = 0; c < 8; c++) acc[r][c] = 0.f;

    for (int d0 = 0; d0 < DD; d0 += 40) {
        __syncthreads();
        // load X chunk [64][40]
        #pragma unroll
        for (int t = 0; t < 10; t++) {
            int idx = t * 256 + tid;
            int r = idx / 40, d = idx % 40;
            Xs[idx] = X[(size_t)(row0 + r) * DD + d0 + d];
        }
        // load W chunk [40][128->132 pad]
        #pragma unroll
        for (int t = 0; t < 20; t++) {
            int idx = t * 256 + tid;
            int d = idx >> 7, e = idx & 127;
            Ws[d * 132 + e] = (e < DD) ? W[(size_t)(d0 + d) * DD + e] : 0.f;
        }
        __syncthreads();

        #pragma unroll 4
        for (int d = 0; d < 40; d++) {
            float4 wa = *(const float4*)&Ws[d * 132 + 4 * tx];
            float4 wb = *(const float4*)&Ws[d * 132 + 64 + 4 * tx];
            float xv[4];
            #pragma unroll
            for (int r = 0; r < 4; r++) xv[r] = Xs[(4 * ty + r) * 40 + d];
            #pragma unroll
            for (int r = 0; r < 4; r++) {
                acc[r][0] = fmaf(xv[r], wa.x, acc[r][0]);
                acc[r][1] = fmaf(xv[r], wa.y, acc[r][1]);
                acc[r][2] = fmaf(xv[r], wa.z, acc[r][2]);
                acc[r][3] = fmaf(xv[r], wa.w, acc[r][3]);
                acc[r][4] = fmaf(xv[r], wb.x, acc[r][4]);
                acc[r][5] = fmaf(xv[r], wb.y, acc[r][5]);
                acc[r][6] = fmaf(xv[r], wb.z, acc[r][6]);
                acc[r][7] = fmaf(xv[r], wb.w, acc[r][7]);
            }
        }
    }

    if (which == 2) {
        // V: natural layout, direct coalesced float4 stores
        #pragma unroll
        for (int r = 0; r < 4; r++) {
            size_t base = (size_t)(row0 + 4 * ty + r) * DD;
            *(float4*)&g_V[base + 4 * tx] =
                make_float4(acc[r][0], acc[r][1], acc[r][2], acc[r][3]);
            if (64 + 4 * tx + 3 < DD)
                *(float4*)&g_V[base + 64 + 4 * tx] =
                    make_float4(acc[r][4], acc[r][5], acc[r][6], acc[r][7]);
        }
    } else {
        // Q/K: transpose through smem, store d-major coalesced along n
        __syncthreads();
        #pragma unroll
        for (int r = 0; r < 4; r++) {
            int rr = 4 * ty + r;
            #pragma unroll
            for (int c = 0; c < 4; c++) Os[rr * 131 + 4 * tx + c]      = acc[r][c];
            #pragma unroll
            for (int c = 0; c < 4; c++) {
                int e = 64 + 4 * tx + c;
                if (e < DD) Os[rr * 131 + e] = acc[r][4 + c];
            }
        }
        __syncthreads();
        float* dst = (which == 0) ? g_Qt : g_Kt;
        const int b = row0 >> 11;
        const int n0 = row0 & 2047;
        #pragma unroll
        for (int t = 0; t < 30; t++) {
            int idx = t * 256 + tid;      // 120*64 = 7680
            int e = idx >> 6, r = idx & 63;
            dst[((size_t)b * DD + e) * N2C + n0 + r] = Os[r * 131 + e];
        }
    }
}

// ================= kernel 2: scores + online softmax stats =================
// grid (N1/64, B), block 256 (tx 16, ty 16). tile 64 i x 128 j per step.
// microtile 4 rows (4*ty..) x 8 cols ({4tx, 64+4tx}).
// smem: Qs[120][64] + Ks[120][128]
#define SC_SMEM ((DD * 64 + DD * 128) * 4)

__global__ __launch_bounds__(256) void score_kernel(
    const int* __restrict__ mask, float* __restrict__ attn)
{
    extern __shared__ float sm[];
    float* Qs = sm;             // [d][64]
    float* Ks = sm + DD * 64;   // [d][128]

    const int b  = blockIdx.y;
    const int i0 = blockIdx.x * TI;
    const int tid = threadIdx.x;
    const int tx = tid & 15, ty = tid >> 4;

    // Qs: [d][r], loaded once
    #pragma unroll
    for (int t = 0; t < 30; t++) {
        int idx = t * 256 + tid;       // 120*64
        int d = idx >> 6, r = idx & 63;
        Qs[idx] = g_Qt[((size_t)b * DD + d) * N1C + i0 + r];
    }

    const float scale = 0.09128709291752768f;  // 1/sqrt(120)
    float m_run[4], l_run[4];
    #pragma unroll
    for (int r = 0; r < 4; r++) { m_run[r] = -CUDART_INF_F; l_run[r] = 0.f; }

    for (int j0 = 0; j0 < N2C; j0 += 128) {
        __syncthreads();
        #pragma unroll
        for (int t = 0; t < 60; t++) {
            int idx = t * 256 + tid;   // 120*128
            int d = idx >> 7, c = idx & 127;
            Ks[idx] = g_Kt[((size_t)b * DD + d) * N2C + j0 + c];
        }
        __syncthreads();

        float acc[4][8];
        #pragma unroll
        for (int r = 0; r < 4; r++)
            #pragma unroll
            for (int c = 0; c < 8; c++) acc[r][c] = 0.f;

        #pragma unroll 4
        for (int d = 0; d < DD; d++) {
            float4 q4 = *(const float4*)&Qs[d * 64 + 4 * ty];
            float4 ka = *(const float4*)&Ks[d * 128 + 4 * tx];
            float4 kb = *(const float4*)&Ks[d * 128 + 64 + 4 * tx];
            float q[4] = {q4.x, q4.y, q4.z, q4.w};
            #pragma unroll
            for (int r = 0; r < 4; r++) {
                acc[r][0] = fmaf(q[r], ka.x, acc[r][0]);
                acc[r][1] = fmaf(q[r], ka.y, acc[r][1]);
                acc[r][2] = fmaf(q[r], ka.z, acc[r][2]);
                acc[r][3] = fmaf(q[r], ka.w, acc[r][3]);
                acc[r][4] = fmaf(q[r], kb.x, acc[r][4]);
                acc[r][5] = fmaf(q[r], kb.y, acc[r][5]);
                acc[r][6] = fmaf(q[r], kb.z, acc[r][6]);
                acc[r][7] = fmaf(q[r], kb.w, acc[r][7]);
            }
        }

        // epilogue: scale + mask, online stats (reduce over 16 tx lanes), stream raw
        #pragma unroll
        for (int r = 0; r < 4; r++) {
            int gi = i0 + 4 * ty + r;
            size_t rowbase = ((size_t)(b * N1C + gi)) * N2C + j0;
            int4 ma = *(const int4*)&mask[rowbase + 4 * tx];
            int4 mb = *(const int4*)&mask[rowbase + 64 + 4 * tx];
            float s[8];
            s[0] = ma.x ? acc[r][0] * scale : -CUDART_INF_F;
            s[1] = ma.y ? acc[r][1] * scale : -CUDART_INF_F;
            s[2] = ma.z ? acc[r][2] * scale : -CUDART_INF_F;
            s[3] = ma.w ? acc[r][3] * scale : -CUDART_INF_F;
            s[4] = mb.x ? acc[r][4] * scale : -CUDART_INF_F;
            s[5] = mb.y ? acc[r][5] * scale : -CUDART_INF_F;
            s[6] = mb.z ? acc[r][6] * scale : -CUDART_INF_F;
            s[7] = mb.w ? acc[r][7] * scale : -CUDART_INF_F;

            float tmax = s[0];
            #pragma unroll
            for (int k = 1; k < 8; k++) tmax = fmaxf(tmax, s[k]);
            #pragma unroll
            for (int o = 8; o; o >>= 1)
                tmax = fmaxf(tmax, __shfl_xor_sync(0xffffffffu, tmax, o));
            float m_new = fmaxf(m_run[r], tmax);

            float se = 0.f;
            #pragma unroll
            for (int k = 0; k < 8; k++) se += __expf(s[k] - m_new);
            #pragma unroll
            for (int o = 8; o; o >>= 1)
                se += __shfl_xor_sync(0xffffffffu, se, o);

            l_run[r] = l_run[r] * __expf(m_run[r] - m_new) + se;
            m_run[r] = m_new;

            *(float4*)&attn[rowbase + 4 * tx]      = make_float4(s[0], s[1], s[2], s[3]);
            *(float4*)&attn[rowbase + 64 + 4 * tx] = make_float4(s[4], s[5], s[6], s[7]);
        }
    }

    if (tx == 0) {
        #pragma unroll
        for (int r = 0; r < 4; r++) {
            int gi = b * N1C + i0 + 4 * ty + r;
            g_M[gi] = m_run[r];
            g_L[gi] = l_run[r];
        }
    }
}

// ================= kernel 3: normalize attn in place + O = P·V =================
// grid (N1/64, B), block 256. tile 64 i x 120 e, j tiles of 64.
// microtile 4 rows x 8 cols ({4tx, 64+4tx}).
// smem: Ps[64][68] + Vs[64][128] + m[64] + linv[64]
#define PV_SMEM ((64 * 68 + TJ * 128 + 2 * 64) * 4)

__global__ __launch_bounds__(256) void pv_kernel(
    float* __restrict__ attn, float* __restrict__ out)
{
    extern __shared__ float sm[];
    float* Ps    = sm;                  // [r][68]
    float* Vs    = Ps + 64 * 68;        // [j][128], cols >=120 zero
    float* mrow  = Vs + TJ * 128;       // [64]
    float* lirow = mrow + 64;           // [64] 1/l

    const int b  = blockIdx.y;
    const int i0 = blockIdx.x * TI;
    const int tid = threadIdx.x;
    const int tx = tid & 15, ty = tid >> 4;

    if (tid < 64) {
        mrow[tid]  = g_M[b * N1C + i0 + tid];
        lirow[tid] = 1.0f / g_L[b * N1C + i0 + tid];
    }

    float acc[4][8];
    #pragma unroll
    for (int r = 0; r < 4; r++)
        #pragma unroll
        for (int c = 0; c < 8; c++) acc[r][c] = 0.f;

    for (int j0 = 0; j0 < N2C; j0 += TJ) {
        __syncthreads();
        // V tile [64][128]
        #pragma unroll
        for (int t = 0; t < 32; t++) {
            int idx = t * 256 + tid;
            int j = idx >> 7, e = idx & 127;
            Vs[idx] = (e < DD) ? g_V[((size_t)(b * N2C + j0 + j)) * DD + e] : 0.f;
        }
        // P: raw scores -> exp(s-m)/l, write final attn + stash in smem
        #pragma unroll
        for (int t = 0; t < 4; t++) {
            int f4 = t * 256 + tid;            // 1024 float4s: 64 rows x 16
            int r  = f4 >> 4;
            int c4 = (f4 & 15) * 4;
            size_t gidx = ((size_t)(b * N1C + i0 + r)) * N2C + j0 + c4;
            float4 sv = *(const float4*)&attn[gidx];
            float m = mrow[r], li = lirow[r];
            float4 p;
            p.x = __expf(sv.x - m) * li;
            p.y = __expf(sv.y - m) * li;
            p.z = __expf(sv.z - m) * li;
            p.w = __expf(sv.w - m) * li;
            *(float4*)&attn[gidx] = p;
            *(float4*)&Ps[r * 68 + c4] = p;
        }
        __syncthreads();

        #pragma unroll 4
        for (int j = 0; j < TJ; j++) {
            float4 va = *(const float4*)&Vs[j * 128 + 4 * tx];
            float4 vb = *(const float4*)&Vs[j * 128 + 64 + 4 * tx];
            float p[4];
            #pragma unroll
            for (int r = 0; r < 4; r++) p[r] = Ps[(4 * ty + r) * 68 + j];
            #pragma unroll
            for (int r = 0; r < 4; r++) {
                acc[r][0] = fmaf(p[r], va.x, acc[r][0]);
                acc[r][1] = fmaf(p[r], va.y, acc[r][1]);
                acc[r][2] = fmaf(p[r], va.z, acc[r][2]);
                acc[r][3] = fmaf(p[r], va.w, acc[r][3]);
                acc[r][4] = fmaf(p[r], vb.x, acc[r][4]);
                acc[r][5] = fmaf(p[r], vb.y, acc[r][5]);
                acc[r][6] = fmaf(p[r], vb.z, acc[r][6]);
                acc[r][7] = fmaf(p[r], vb.w, acc[r][7]);
            }
        }
    }

    #pragma unroll
    for (int r = 0; r < 4; r++) {
        size_t base = ((size_t)(b * N1C + i0 + 4 * ty + r)) * DD;
        *(float4*)&out[base + 4 * tx] =
            make_float4(acc[r][0], acc[r][1], acc[r][2], acc[r][3]);
        if (64 + 4 * tx + 3 < DD)
            *(float4*)&out[base + 64 + 4 * tx] =
                make_float4(acc[r][4], acc[r][5], acc[r][6], acc[r][7]);
    }
}

// ================= launch =================
extern "C" void kernel_launch(void* const* d_in, const int* in_sizes, int n_in,
                              void* d_out, int out_size)
{
    const float* x1  = (const float*)d_in[0];
    const float* x2  = (const float*)d_in[1];
    const int*   msk = (const int*)  d_in[2];
    const float* Wq  = (const float*)d_in[3];
    const float* Wk  = (const float*)d_in[4];
    const float* Wv  = (const float*)d_in[5];

    float* outO = (float*)d_out;                    // [B,N1,D]
    float* outP = outO + (size_t)BB * N1C * DD;     // [B,N1,N2]

    cudaFuncSetAttribute(proj_kernel,  cudaFuncAttributeMaxDynamicSharedMemorySize, PROJ_SMEM);
    cudaFuncSetAttribute(score_kernel, cudaFuncAttributeMaxDynamicSharedMemorySize, SC_SMEM);
    cudaFuncSetAttribute(pv_kernel,    cudaFuncAttributeMaxDynamicSharedMemorySize, PV_SMEM);

    proj_kernel <<<dim3(NROW / 64, 3), 256, PROJ_SMEM>>>(x1, x2, Wq, Wk, Wv);
    score_kernel<<<dim3(N1C / TI, BB), 256, SC_SMEM  >>>(msk, outP);
    pv_kernel   <<<dim3(N1C / TI, BB), 256, PV_SMEM  >>>(outP, outO);
}